// round 10
// baseline (speedup 1.0000x reference)
#include <cuda_runtime.h>
#include <math.h>

// Problem dims
#define T_  128
#define B_  64
#define V_  8192
#define H_  2048
#define VH_ 10240   // V_ + H_

#define NCTA 128          // persistent CTAs, one per SM (h-slice of 16)
#define TPB  512
#define HW   16           // h rows per CTA
#define BK   128          // k chunk staged per double-buffer slot
#define WS_STRIDE 2052    // 2048 + 4 pad (16B-aligned rows)
#define AS_STRIDE 132     // 128 + 4 pad (16B-aligned rows)

// State history: g_states[t][b][h]  (64 MB device-global scratch)
__device__ __align__(16) float g_states[(size_t)T_ * B_ * H_];

// Grid barrier state (zero-initialized)
__device__ unsigned g_bar_gen;
__device__ unsigned g_bar_cnt;

// ---------------------------------------------------------------------------
// helpers
// ---------------------------------------------------------------------------
__device__ __forceinline__ void ffma2(unsigned long long& d,
                                      unsigned long long a,
                                      unsigned long long b)
{
    asm("fma.rn.f32x2 %0, %1, %2, %0;" : "+l"(d) : "l"(a), "l"(b));
}

__device__ __forceinline__ float f2_lo(unsigned long long v)
{ return __int_as_float((int)(unsigned)(v & 0xffffffffu)); }
__device__ __forceinline__ float f2_hi(unsigned long long v)
{ return __int_as_float((int)(unsigned)(v >> 32)); }

__device__ __forceinline__ void cp_async16(void* sdst, const void* gsrc)
{
    unsigned sa = (unsigned)__cvta_generic_to_shared(sdst);
    asm volatile("cp.async.cg.shared.global [%0], [%1], 16;\n" :: "r"(sa), "l"(gsrc));
}
__device__ __forceinline__ void cp_commit()
{ asm volatile("cp.async.commit_group;\n"); }
template<int N> __device__ __forceinline__ void cp_wait()
{ asm volatile("cp.async.wait_group %0;\n" :: "n"(N)); }

__device__ __forceinline__ void grid_barrier()
{
    __syncthreads();
    if (threadIdx.x == 0) {
        __threadfence();
        unsigned gen = *(volatile unsigned*)&g_bar_gen;
        unsigned t = atomicAdd(&g_bar_cnt, 1u);
        if (t == NCTA - 1) {
            atomicExch(&g_bar_cnt, 0u);
            __threadfence();
            atomicAdd(&g_bar_gen, 1u);
        } else {
            while (*(volatile unsigned*)&g_bar_gen == gen) { }
        }
        __threadfence();
    }
    __syncthreads();
}

// ---------------------------------------------------------------------------
// Persistent recurrence kernel, v3: 512 threads, 4b x 4h tile, 8-way k-split.
// grid = 128 CTAs x 512 threads. CTA owns h rows [bid*16, bid*16+16).
// Thread mapping: ks = tid&7 (k split), hq = (tid>>3)&3 (h quad),
//                 bq = tid>>5 (b quad).  k interleave: 32 floats/group,
//                 this thread takes floats [g*32 + ks*4, +4).
// ---------------------------------------------------------------------------
extern __shared__ float s_mem[];

__global__ __launch_bounds__(TPB, 1)
void rnn_persistent(const int* __restrict__ tok_all,     // [T_][B_]
                    const float* __restrict__ hidden_w,  // [H_][VH_]
                    const float* __restrict__ hidden_b)  // [H_]
{
    float* ws   = s_mem;                    // [16][WS_STRIDE]
    float* abuf = s_mem + HW * WS_STRIDE;   // 2 x [64][AS_STRIDE]

    const int tid = threadIdx.x;
    const int h0  = blockIdx.x * HW;

    // preload W_hh slice into smem (once)
    for (int r = 0; r < HW; ++r) {
        const float* src = hidden_w + (size_t)(h0 + r) * VH_ + V_;
        float*       dst = ws + r * WS_STRIDE;
        for (int idx = tid; idx < H_ / 4; idx += TPB)
            *(float4*)(dst + idx * 4) = *(const float4*)(src + idx * 4);
    }
    __syncthreads();

    // compute mapping
    const int ks = tid & 7;             // 0..7
    const int hq = (tid >> 3) & 3;      // 0..3
    const int bq = tid >> 5;            // 0..15
    const bool writer = (ks == 0);

    // staging mapping: 64 rows x 32 float4 cols, 512 threads -> 4 elems each
    const int st_c4 = tid & 31;
    const int st_r0 = tid >> 5;         // 0..15 (rows r0 + 16i)

    // biases for this thread's 4 h values (h0 + hq*4 .. +3)
    const float4 bias4 = *(const float4*)(hidden_b + h0 + hq * 4);
    // embedding row pointers
    const float* wrow0 = hidden_w + (size_t)(h0 + hq * 4 + 0) * VH_;
    const float* wrow1 = hidden_w + (size_t)(h0 + hq * 4 + 1) * VH_;
    const float* wrow2 = hidden_w + (size_t)(h0 + hq * 4 + 2) * VH_;
    const float* wrow3 = hidden_w + (size_t)(h0 + hq * 4 + 3) * VH_;

    for (int t = 0; t < T_; ++t) {
        unsigned long long acc[4][4];
#pragma unroll
        for (int bi = 0; bi < 4; ++bi)
#pragma unroll
            for (int hj = 0; hj < 4; ++hj) acc[bi][hj] = 0ull;

        if (t > 0) {
            const float* prev = g_states + (size_t)(t - 1) * B_ * H_;

            // prefetch chunk 0 into buffer 0
            {
                float* buf = abuf;
#pragma unroll
                for (int i = 0; i < 4; ++i) {
                    int r = st_r0 + 16 * i;
                    cp_async16(buf + r * AS_STRIDE + st_c4 * 4,
                               prev + (size_t)r * H_ + st_c4 * 4);
                }
                cp_commit();
            }

            const int NCH = H_ / BK;   // 16
            for (int c = 0; c < NCH; ++c) {
                if (c + 1 < NCH) {
                    float* buf = abuf + ((c + 1) & 1) * (64 * AS_STRIDE);
                    const int k0 = (c + 1) * BK;
#pragma unroll
                    for (int i = 0; i < 4; ++i) {
                        int r = st_r0 + 16 * i;
                        cp_async16(buf + r * AS_STRIDE + st_c4 * 4,
                                   prev + (size_t)r * H_ + k0 + st_c4 * 4);
                    }
                    cp_commit();
                    cp_wait<1>();
                } else {
                    cp_wait<0>();
                }
                __syncthreads();

                const float* buf = abuf + (c & 1) * (64 * AS_STRIDE);
                const float* Abase = buf + (bq * 4) * AS_STRIDE + ks * 4;
                const float* Wbase = ws + (hq * 4) * WS_STRIDE + c * BK + ks * 4;

#pragma unroll
                for (int g = 0; g < 4; ++g) {          // 4 groups of 32 k
                    const int ko = g * 32;
                    ulonglong2 a0 = *(const ulonglong2*)(Abase + 0 * AS_STRIDE + ko);
                    ulonglong2 a1 = *(const ulonglong2*)(Abase + 1 * AS_STRIDE + ko);
                    ulonglong2 a2 = *(const ulonglong2*)(Abase + 2 * AS_STRIDE + ko);
                    ulonglong2 a3 = *(const ulonglong2*)(Abase + 3 * AS_STRIDE + ko);
                    ulonglong2 w0 = *(const ulonglong2*)(Wbase + 0 * WS_STRIDE + ko);
                    ulonglong2 w1 = *(const ulonglong2*)(Wbase + 1 * WS_STRIDE + ko);
                    ulonglong2 w2 = *(const ulonglong2*)(Wbase + 2 * WS_STRIDE + ko);
                    ulonglong2 w3 = *(const ulonglong2*)(Wbase + 3 * WS_STRIDE + ko);

                    ffma2(acc[0][0], a0.x, w0.x); ffma2(acc[0][0], a0.y, w0.y);
                    ffma2(acc[0][1], a0.x, w1.x); ffma2(acc[0][1], a0.y, w1.y);
                    ffma2(acc[0][2], a0.x, w2.x); ffma2(acc[0][2], a0.y, w2.y);
                    ffma2(acc[0][3], a0.x, w3.x); ffma2(acc[0][3], a0.y, w3.y);
                    ffma2(acc[1][0], a1.x, w0.x); ffma2(acc[1][0], a1.y, w0.y);
                    ffma2(acc[1][1], a1.x, w1.x); ffma2(acc[1][1], a1.y, w1.y);
                    ffma2(acc[1][2], a1.x, w2.x); ffma2(acc[1][2], a1.y, w2.y);
                    ffma2(acc[1][3], a1.x, w3.x); ffma2(acc[1][3], a1.y, w3.y);
                    ffma2(acc[2][0], a2.x, w0.x); ffma2(acc[2][0], a2.y, w0.y);
                    ffma2(acc[2][1], a2.x, w1.x); ffma2(acc[2][1], a2.y, w1.y);
                    ffma2(acc[2][2], a2.x, w2.x); ffma2(acc[2][2], a2.y, w2.y);
                    ffma2(acc[2][3], a2.x, w3.x); ffma2(acc[2][3], a2.y, w3.y);
                    ffma2(acc[3][0], a3.x, w0.x); ffma2(acc[3][0], a3.y, w0.y);
                    ffma2(acc[3][1], a3.x, w1.x); ffma2(acc[3][1], a3.y, w1.y);
                    ffma2(acc[3][2], a3.x, w2.x); ffma2(acc[3][2], a3.y, w2.y);
                    ffma2(acc[3][3], a3.x, w3.x); ffma2(acc[3][3], a3.y, w3.y);
                }
                __syncthreads();
            }
        }

        // reduce over 8 ks lanes (lane bits 0..2) and write
        float res[4][4];
#pragma unroll
        for (int bi = 0; bi < 4; ++bi) {
#pragma unroll
            for (int hj = 0; hj < 4; ++hj) {
                float s = f2_lo(acc[bi][hj]) + f2_hi(acc[bi][hj]);
                s += __shfl_xor_sync(0xffffffffu, s, 1);
                s += __shfl_xor_sync(0xffffffffu, s, 2);
                s += __shfl_xor_sync(0xffffffffu, s, 4);
                res[bi][hj] = s;
            }
        }

        if (writer) {
            float* next = g_states + (size_t)t * B_ * H_;
#pragma unroll
            for (int bi = 0; bi < 4; ++bi) {
                const int b = bq * 4 + bi;
                int tk = tok_all[t * B_ + b];
                tk = (tk < 0) ? 0 : ((tk >= V_) ? V_ - 1 : tk);
                float4 v;
                v.x = tanhf(res[bi][0] + bias4.x + wrow0[tk]);
                v.y = tanhf(res[bi][1] + bias4.y + wrow1[tk]);
                v.z = tanhf(res[bi][2] + bias4.z + wrow2[tk]);
                v.w = tanhf(res[bi][3] + bias4.w + wrow3[tk]);
                *(float4*)(next + (size_t)b * H_ + h0 + hq * 4) = v;
            }
        }

        grid_barrier();
    }
}

// ---------------------------------------------------------------------------
// Batched output projection (R2 scalar version, measured-good):
//   out[m, v] = output_b[v] + sum_h S[m,h] * output_w[v,h]
// BM=BN=128, BK=8, 256 threads, 8x8 microtile.
// ---------------------------------------------------------------------------
__global__ void out_gemm_kernel(const float* __restrict__ W,   // [V_][H_]
                                const float* __restrict__ ob,  // [V_]
                                float* __restrict__ out)       // [T_*B_][V_]
{
    __shared__ float As[8][128];  // [k][m]
    __shared__ float Bs[8][128];  // [k][n]

    const float* S = g_states;    // [T_*B_][H_]

    const int tid = threadIdx.x;
    const int m0  = blockIdx.y * 128;
    const int n0  = blockIdx.x * 128;
    const int tx  = tid & 15;
    const int ty  = tid >> 4;
    const int mr  = ty * 8;
    const int nr  = tx * 8;

    float acc[8][8];
#pragma unroll
    for (int i = 0; i < 8; i++)
#pragma unroll
        for (int j = 0; j < 8; j++) acc[i][j] = 0.0f;

    const int lrow = tid >> 1;        // 0..127
    const int lk   = (tid & 1) * 4;   // 0 or 4

    for (int k0 = 0; k0 < H_; k0 += 8) {
        float4 av = *(const float4*)(S + (size_t)(m0 + lrow) * H_ + k0 + lk);
        float4 bv = *(const float4*)(W + (size_t)(n0 + lrow) * H_ + k0 + lk);
        As[lk + 0][lrow] = av.x; As[lk + 1][lrow] = av.y;
        As[lk + 2][lrow] = av.z; As[lk + 3][lrow] = av.w;
        Bs[lk + 0][lrow] = bv.x; Bs[lk + 1][lrow] = bv.y;
        Bs[lk + 2][lrow] = bv.z; Bs[lk + 3][lrow] = bv.w;
        __syncthreads();
#pragma unroll
        for (int kk = 0; kk < 8; kk++) {
            float a[8], b[8];
            *(float4*)&a[0] = *(const float4*)&As[kk][mr];
            *(float4*)&a[4] = *(const float4*)&As[kk][mr + 4];
            *(float4*)&b[0] = *(const float4*)&Bs[kk][nr];
            *(float4*)&b[4] = *(const float4*)&Bs[kk][nr + 4];
#pragma unroll
            for (int i = 0; i < 8; i++)
#pragma unroll
                for (int j = 0; j < 8; j++)
                    acc[i][j] += a[i] * b[j];
        }
        __syncthreads();
    }

#pragma unroll
    for (int i = 0; i < 8; i++) {
        const int m = m0 + mr + i;
#pragma unroll
        for (int j = 0; j < 8; j += 4) {
            const int n = n0 + nr + j;
            float4 o;
            o.x = acc[i][j + 0] + ob[n + 0];
            o.y = acc[i][j + 1] + ob[n + 1];
            o.z = acc[i][j + 2] + ob[n + 2];
            o.w = acc[i][j + 3] + ob[n + 3];
            *(float4*)(out + (size_t)m * V_ + n) = o;
        }
    }
}

// Copy final state (g_states[T_-1]) to the tail of the output buffer.
__global__ void copy_final_state_kernel(float* __restrict__ dst)
{
    const float* src = g_states + (size_t)(T_ - 1) * B_ * H_;
    int idx = blockIdx.x * blockDim.x + threadIdx.x;
    if (idx < B_ * H_) dst[idx] = src[idx];
}

extern "C" void kernel_launch(void* const* d_in, const int* in_sizes, int n_in,
                              void* d_out, int out_size)
{
    const int*   inputs   = (const int*)d_in[0];     // [T_][B_] int32
    const float* hidden_w = (const float*)d_in[1];   // [H_][VH_]
    const float* hidden_b = (const float*)d_in[2];   // [H_]
    const float* output_w = (const float*)d_in[3];   // [V_][H_]
    const float* output_b = (const float*)d_in[4];   // [V_]
    float*       out      = (float*)d_out;

    (void)in_sizes; (void)n_in;

    const int smem_bytes = (HW * WS_STRIDE + 2 * 64 * AS_STRIDE) * sizeof(float);
    cudaFuncSetAttribute(rnn_persistent,
                         cudaFuncAttributeMaxDynamicSharedMemorySize, smem_bytes);

    // One persistent launch runs all 128 recurrence steps.
    rnn_persistent<<<NCTA, TPB, smem_bytes>>>(inputs, hidden_w, hidden_b);

    // Batched output projection over all timesteps
    dim3 grid(V_ / 128, (T_ * B_) / 128);
    out_gemm_kernel<<<grid, 256>>>(output_w, output_b, out);

    // Final state, if the output buffer includes it (outputs first, then final_state)
    const size_t outputs_elems = (size_t)T_ * B_ * V_;
    if ((size_t)out_size >= outputs_elems + (size_t)B_ * H_) {
        copy_final_state_kernel<<<(B_ * H_ + 255) / 256, 256>>>(out + outputs_elems);
    }
}